// round 3
// baseline (speedup 1.0000x reference)
#include <cuda_runtime.h>
#include <math.h>
#include <stdint.h>

#define BATCH 4
#define SEQ   512
#define TOKS  (BATCH*SEQ)      // 2048
#define DH    1600
#define NHEADS 50
#define PH    32
#define NREL  100
#define KT    64               // key tile in attention

// ------------------------------------------------------------------
// Scratch (static __device__ — no allocation allowed)
// ------------------------------------------------------------------
__device__ float g_Q[TOKS*DH];
__device__ float g_K[TOKS*DH];
__device__ float g_V[TOKS*DH];
__device__ float g_ctx[TOKS*DH];
__device__ float g_attn[TOKS*DH];
__device__ float g_h1[TOKS*DH];

// ------------------------------------------------------------------
// SGEMM: C[M,N] = A[M,K] @ B[K,N] + bias[N], optional exact GELU.
// BM=128, BN=64, BK=16, 128 threads, 8x8 per-thread microtile.
// All dims are exact multiples (M=2048, N=1600, K=1600) -> no bounds checks.
// ------------------------------------------------------------------
__global__ __launch_bounds__(128) void sgemm_bias_act(
    const float* __restrict__ A, const float* __restrict__ B,
    const float* __restrict__ bias, float* __restrict__ C,
    int M, int N, int K, int act)
{
    __shared__ float As[16][128];   // transposed A tile: As[k][m]
    __shared__ float Bs[16][64];    // Bs[k][n]

    const int tid = threadIdx.x;
    const int tx  = tid & 7;        // 0..7  -> 8 cols of 8
    const int ty  = tid >> 3;       // 0..15 -> 16 rows of 8
    const int bm  = blockIdx.y * 128;
    const int bn  = blockIdx.x * 64;

    float acc[8][8];
    #pragma unroll
    for (int i = 0; i < 8; ++i)
        #pragma unroll
        for (int j = 0; j < 8; ++j) acc[i][j] = 0.f;

    // A-tile load mapping: 512 float4 total, 4 per thread
    const int arow0 = tid >> 2;         // row = f/4, f = tid + 128*i
    const int akc   = (tid & 3) * 4;    // k offset within tile
    // B-tile load mapping: 256 float4 total, 2 per thread
    const int brow0 = tid >> 4;         // row = f/16
    const int bnc   = (tid & 15) * 4;   // n offset within tile

    for (int k0 = 0; k0 < K; k0 += 16) {
        #pragma unroll
        for (int i = 0; i < 4; ++i) {
            int row = arow0 + i * 32;
            float4 v = *(const float4*)(A + (size_t)(bm + row) * K + k0 + akc);
            As[akc + 0][row] = v.x;
            As[akc + 1][row] = v.y;
            As[akc + 2][row] = v.z;
            As[akc + 3][row] = v.w;
        }
        #pragma unroll
        for (int i = 0; i < 2; ++i) {
            int row = brow0 + i * 8;
            float4 v = *(const float4*)(B + (size_t)(k0 + row) * N + bn + bnc);
            *(float4*)&Bs[row][bnc] = v;
        }
        __syncthreads();

        #pragma unroll
        for (int kk = 0; kk < 16; ++kk) {
            float a[8], bb[8];
            *(float4*)&a[0]  = *(const float4*)&As[kk][ty * 8];
            *(float4*)&a[4]  = *(const float4*)&As[kk][ty * 8 + 4];
            *(float4*)&bb[0] = *(const float4*)&Bs[kk][tx * 8];
            *(float4*)&bb[4] = *(const float4*)&Bs[kk][tx * 8 + 4];
            #pragma unroll
            for (int i = 0; i < 8; ++i)
                #pragma unroll
                for (int j = 0; j < 8; ++j)
                    acc[i][j] = fmaf(a[i], bb[j], acc[i][j]);
        }
        __syncthreads();
    }

    #pragma unroll
    for (int i = 0; i < 8; ++i) {
        int row = bm + ty * 8 + i;
        #pragma unroll
        for (int j = 0; j < 8; ++j) {
            float x = acc[i][j] + bias[bn + tx * 8 + j];
            if (act) {
                // exact GELU: 0.5*x*(1+erf(x/sqrt(2)))
                x = 0.5f * x * (1.f + erff(x * 0.70710678118654752f));
            }
            acc[i][j] = x;
        }
        *(float4*)(C + (size_t)row * N + bn + tx * 8)     = *(float4*)&acc[i][0];
        *(float4*)(C + (size_t)row * N + bn + tx * 8 + 4) = *(float4*)&acc[i][4];
    }
}

// ------------------------------------------------------------------
// Fused relation-aware attention. One query per thread; flash-style
// online softmax. rel_k/rel_v embedding tables live in SMEM (stride
// PH+1=33 so per-thread relation gathers land on distinct banks:
// bank = (r + d) mod 32).
//   score[q,k] = (q . (K[k] + rel_k[rm[b,q,k]])) / sqrt(PH)
//   ctx[q]     = sum_k softmax(score) * (V[k] + rel_v[rm[b,q,k]])
// ------------------------------------------------------------------
__global__ __launch_bounds__(256, 2) void attn_kernel(
    const float* __restrict__ Q, const float* __restrict__ Kg,
    const float* __restrict__ Vg,
    const float* __restrict__ relk, const float* __restrict__ relv,
    const int* __restrict__ rm, float* __restrict__ ctxout)
{
    __shared__ float Ks[KT][PH];
    __shared__ float Vs[KT][PH];
    __shared__ float rk[NREL][PH + 1];
    __shared__ float rv[NREL][PH + 1];

    const int bh  = blockIdx.x;
    const int b   = bh / NHEADS;
    const int h   = bh % NHEADS;
    const int tid = threadIdx.x;
    const int q   = blockIdx.y * 256 + tid;

    // stage relation embedding tables (100x32 each)
    for (int i = tid; i < NREL * PH; i += 256) {
        int r = i >> 5, d = i & 31;
        rk[r][d] = relk[i];
        rv[r][d] = relv[i];
    }

    // per-thread query vector
    float qv[PH];
    {
        const float* qp = Q + (size_t)(b * SEQ + q) * DH + h * PH;
        #pragma unroll
        for (int d = 0; d < PH; d += 4) {
            float4 t = *(const float4*)(qp + d);
            qv[d] = t.x; qv[d + 1] = t.y; qv[d + 2] = t.z; qv[d + 3] = t.w;
        }
    }

    float m = -1e30f, l = 0.f;
    float ctx[PH];
    #pragma unroll
    for (int d = 0; d < PH; ++d) ctx[d] = 0.f;

    const float scale = 0.1767766952966369f;  // 1/sqrt(32)
    const int* rmrow = rm + ((size_t)b * SEQ + q) * SEQ;

    for (int kt = 0; kt < SEQ; kt += KT) {
        __syncthreads();
        // load K/V tile: KT*PH floats each, float4-vectorized, coalesced
        for (int f = tid; f < KT * PH / 4; f += 256) {
            int row = f >> 3;
            int c   = (f & 7) * 4;
            size_t gidx = (size_t)(b * SEQ + kt + row) * DH + h * PH + c;
            ((float4*)Ks)[f] = *(const float4*)(Kg + gidx);
            ((float4*)Vs)[f] = *(const float4*)(Vg + gidx);
        }
        __syncthreads();

        for (int kk0 = 0; kk0 < KT; kk0 += 8) {
            int rr[8];
            float s[8];
            {
                int4 t0 = *(const int4*)(rmrow + kt + kk0);
                int4 t1 = *(const int4*)(rmrow + kt + kk0 + 4);
                rr[0] = t0.x; rr[1] = t0.y; rr[2] = t0.z; rr[3] = t0.w;
                rr[4] = t1.x; rr[5] = t1.y; rr[6] = t1.z; rr[7] = t1.w;
            }
            float tmax = -1e30f;
            #pragma unroll
            for (int j = 0; j < 8; ++j) {
                const float* kv  = Ks[kk0 + j];   // broadcast across warp
                const float* rkv = rk[rr[j]];     // bank-spread gather
                float a = 0.f;
                #pragma unroll
                for (int d = 0; d < PH; ++d)
                    a = fmaf(qv[d], kv[d] + rkv[d], a);
                s[j] = a * scale;
                tmax = fmaxf(tmax, s[j]);
            }
            if (tmax > m) {
                float alpha = __expf(m - tmax);
                m = tmax;
                l *= alpha;
                #pragma unroll
                for (int d = 0; d < PH; ++d) ctx[d] *= alpha;
            }
            #pragma unroll
            for (int j = 0; j < 8; ++j) {
                float p = __expf(s[j] - m);
                l += p;
                const float* vv  = Vs[kk0 + j];
                const float* rvv = rv[rr[j]];
                #pragma unroll
                for (int d = 0; d < PH; ++d)
                    ctx[d] = fmaf(p, vv[d] + rvv[d], ctx[d]);
            }
        }
    }

    float inv = 1.f / l;
    float* op = ctxout + (size_t)(b * SEQ + q) * DH + h * PH;
    #pragma unroll
    for (int d = 0; d < PH; d += 4) {
        float4 t;
        t.x = ctx[d] * inv; t.y = ctx[d + 1] * inv;
        t.z = ctx[d + 2] * inv; t.w = ctx[d + 3] * inv;
        *(float4*)(op + d) = t;
    }
}

// ------------------------------------------------------------------
// Launch: 3 projection GEMMs -> attention -> Wo -> W1(+gelu) -> W2
// All on the default stream; graph-capturable (launches only).
// ------------------------------------------------------------------
extern "C" void kernel_launch(void* const* d_in, const int* in_sizes, int n_in,
                              void* d_out, int out_size)
{
    const float* hidden = (const float*)d_in[0];
    const float* Wq = (const float*)d_in[1];
    const float* bq = (const float*)d_in[2];
    const float* Wk = (const float*)d_in[3];
    const float* bk = (const float*)d_in[4];
    const float* Wv = (const float*)d_in[5];
    const float* bv = (const float*)d_in[6];
    const float* Wo = (const float*)d_in[7];
    const float* bo = (const float*)d_in[8];
    const float* rke = (const float*)d_in[9];
    const float* rve = (const float*)d_in[10];
    const float* W1 = (const float*)d_in[11];
    const float* b1 = (const float*)d_in[12];
    const float* W2 = (const float*)d_in[13];
    const float* b2 = (const float*)d_in[14];
    const int*   rm = (const int*)d_in[15];
    float* out = (float*)d_out;

    float *Qb, *Kb, *Vb, *Cb, *Ab, *Hb;
    cudaGetSymbolAddress((void**)&Qb, g_Q);
    cudaGetSymbolAddress((void**)&Kb, g_K);
    cudaGetSymbolAddress((void**)&Vb, g_V);
    cudaGetSymbolAddress((void**)&Cb, g_ctx);
    cudaGetSymbolAddress((void**)&Ab, g_attn);
    cudaGetSymbolAddress((void**)&Hb, g_h1);

    dim3 gg(DH / 64, TOKS / 128);   // (25, 16)

    sgemm_bias_act<<<gg, 128>>>(hidden, Wq, bq, Qb, TOKS, DH, DH, 0);
    sgemm_bias_act<<<gg, 128>>>(hidden, Wk, bk, Kb, TOKS, DH, DH, 0);
    sgemm_bias_act<<<gg, 128>>>(hidden, Wv, bv, Vb, TOKS, DH, DH, 0);

    dim3 ag(BATCH * NHEADS, SEQ / 256);  // (200, 2)
    attn_kernel<<<ag, 256>>>(Qb, Kb, Vb, rke, rve, rm, Cb);

    sgemm_bias_act<<<gg, 128>>>(Cb, Wo, bo, Ab, TOKS, DH, DH, 0);
    sgemm_bias_act<<<gg, 128>>>(Ab, W1, b1, Hb, TOKS, DH, DH, 1);
    sgemm_bias_act<<<gg, 128>>>(Hb, W2, b2, out, TOKS, DH, DH, 0);
}